// round 1
// baseline (speedup 1.0000x reference)
#include <cuda_runtime.h>
#include <cuda_bf16.h>
#include <cstdint>

// Problem constants
#define BATCH 4
#define SEQ   8192
#define DIM   4096
#define NEXP  64
#define CAP   256
#define ROWS  (BATCH * SEQ)      // 32768

// GEMM tiling
#define TILE_R 128
#define KT     64
#define NTILES (DIM / KT)        // 64

// smem layout (floats): Xs double buffer [2][128][64], Ws double buffer [2][64][66]
#define XS_BUF_STRIDE (TILE_R * KT)          // 8192
#define WS_OFF        (2 * XS_BUF_STRIDE)    // 16384
#define WS_BUF_STRIDE (NEXP * (KT + 2))      // 4224
#define SMEM_FLOATS   (WS_OFF + 2 * WS_BUF_STRIDE)   // 24832
#define SMEM_BYTES    (SMEM_FLOATS * 4)              // 99328

// scratch: transposed probs [B][E][S]  (8 MB device global — allocation-free)
__device__ float g_probsT[(size_t)BATCH * NEXP * SEQ];

// ---------------------------------------------------------------------------
// helpers
// ---------------------------------------------------------------------------
__device__ __forceinline__ void cp_async16(void* smem_dst, const void* gmem_src) {
    unsigned s = (unsigned)__cvta_generic_to_shared(smem_dst);
    asm volatile("cp.async.cg.shared.global [%0], [%1], 16;\n" :: "r"(s), "l"(gmem_src) : "memory");
}
__device__ __forceinline__ void cp_async8(void* smem_dst, const void* gmem_src) {
    unsigned s = (unsigned)__cvta_generic_to_shared(smem_dst);
    asm volatile("cp.async.ca.shared.global [%0], [%1], 8;\n" :: "r"(s), "l"(gmem_src) : "memory");
}
__device__ __forceinline__ void cp_commit() {
    asm volatile("cp.async.commit_group;\n" ::: "memory");
}

// packed fp32x2 FMA (Blackwell): 2 exact fp32 FMAs per instruction, full-rate pipe
__device__ __forceinline__ float2 ffma2(float2 a, float2 b, float2 c) {
    float2 d;
    asm("{\n\t"
        ".reg .b64 ra, rb, rc, rd;\n\t"
        "mov.b64 ra, {%2, %3};\n\t"
        "mov.b64 rb, {%4, %5};\n\t"
        "mov.b64 rc, {%6, %7};\n\t"
        "fma.rn.f32x2 rd, ra, rb, rc;\n\t"
        "mov.b64 {%0, %1}, rd;\n\t"
        "}"
        : "=f"(d.x), "=f"(d.y)
        : "f"(a.x), "f"(a.y), "f"(b.x), "f"(b.y), "f"(c.x), "f"(c.y));
    return d;
}

// ---------------------------------------------------------------------------
// Kernel 1: router GEMM (logits = X @ W^T), fused softmax, writes
//   logits [B,S,E], probs [B,S,E], and transposed probsT [B,E,S] (scratch).
// Grid: 256 blocks (one per 128-row tile), 256 threads, 2 blocks/SM.
// ---------------------------------------------------------------------------
__global__ void __launch_bounds__(256, 2)
router_gemm_kernel(const float* __restrict__ X, const float* __restrict__ W,
                   float* __restrict__ probs_out, float* __restrict__ logits_out)
{
    extern __shared__ float sm[];
    float* Xs = sm;
    float* Ws = sm + WS_OFF;

    const int tid  = threadIdx.x;
    const int tx   = tid & 15;   // expert group: cols tx + 16j, j=0..3
    const int ty   = tid >> 4;   // row group: rows ty + 16i, i=0..7
    const int row0 = blockIdx.x * TILE_R;

    float2 acc[8][4];
#pragma unroll
    for (int i = 0; i < 8; i++)
#pragma unroll
        for (int j = 0; j < 4; j++) acc[i][j] = make_float2(0.f, 0.f);

    auto prefetch = [&](int buf, int k0) {
        float* xd = Xs + buf * XS_BUF_STRIDE;
#pragma unroll
        for (int m = 0; m < 8; m++) {
            int f = tid + m * 256;        // 0..2047 float4 slots
            int r = f >> 4;               // row (16 float4 per row)
            int c4 = f & 15;
            cp_async16(xd + r * KT + c4 * 4,
                       X + (size_t)(row0 + r) * DIM + k0 + c4 * 4);
        }
        float* wd = Ws + buf * WS_BUF_STRIDE;
#pragma unroll
        for (int m = 0; m < 8; m++) {
            int f = tid + m * 256;        // 0..2047 float2 slots
            int e = f >> 5;               // expert row (32 float2 per row)
            int c2 = f & 31;
            cp_async8(wd + e * (KT + 2) + c2 * 2,
                      W + (size_t)e * DIM + k0 + c2 * 2);
        }
        cp_commit();
    };

    prefetch(0, 0);
    int buf = 0;
    for (int t = 0; t < NTILES; t++) {
        __syncthreads();  // all warps done reading buf^1 before overwriting it
        if (t + 1 < NTILES) {
            prefetch(buf ^ 1, (t + 1) * KT);
            asm volatile("cp.async.wait_group 1;\n" ::: "memory");
        } else {
            asm volatile("cp.async.wait_group 0;\n" ::: "memory");
        }
        __syncthreads();  // tile t data visible to all

        const float* Xb = Xs + buf * XS_BUF_STRIDE;
        const float* Wb = Ws + buf * WS_BUF_STRIDE;
#pragma unroll 8
        for (int kk = 0; kk < KT; kk += 2) {
            float2 xv[8], wv[4];
#pragma unroll
            for (int i = 0; i < 8; i++)
                xv[i] = *(const float2*)(Xb + (ty + 16 * i) * KT + kk);
#pragma unroll
            for (int j = 0; j < 4; j++)
                wv[j] = *(const float2*)(Wb + (tx + 16 * j) * (KT + 2) + kk);
#pragma unroll
            for (int i = 0; i < 8; i++)
#pragma unroll
                for (int j = 0; j < 4; j++)
                    acc[i][j] = ffma2(xv[i], wv[j], acc[i][j]);
        }
        buf ^= 1;
    }
    __syncthreads();  // compute fully done; smem reusable for transpose

    // Epilogue: softmax over E=64 per row (row spread across 16 lanes, 4 cols each),
    // write logits + probs, and stage probs transposed in smem.
    float* Ps = sm;  // [64][130]
#pragma unroll
    for (int i = 0; i < 8; i++) {
        float v[4];
#pragma unroll
        for (int j = 0; j < 4; j++) v[j] = acc[i][j].x + acc[i][j].y;
        float mx = fmaxf(fmaxf(v[0], v[1]), fmaxf(v[2], v[3]));
#pragma unroll
        for (int o = 1; o < 16; o <<= 1)
            mx = fmaxf(mx, __shfl_xor_sync(0xFFFFFFFFu, mx, o));
        float ex[4], ssum = 0.f;
#pragma unroll
        for (int j = 0; j < 4; j++) { ex[j] = expf(v[j] - mx); ssum += ex[j]; }
#pragma unroll
        for (int o = 1; o < 16; o <<= 1)
            ssum += __shfl_xor_sync(0xFFFFFFFFu, ssum, o);
        float inv = 1.0f / ssum;

        int row = row0 + ty + 16 * i;
#pragma unroll
        for (int j = 0; j < 4; j++) {
            int col = tx + 16 * j;
            float p = ex[j] * inv;
            logits_out[(size_t)row * NEXP + col] = v[j];
            probs_out[(size_t)row * NEXP + col] = p;
            Ps[col * 130 + ty + 16 * i] = p;   // conflict-free: stride 130
        }
    }
    __syncthreads();

    // Coalesced write of the transposed tile into g_probsT [b][e][s]
    const int bb = row0 >> 13;          // row0 / 8192
    const int s0 = row0 & (SEQ - 1);
#pragma unroll
    for (int m = 0; m < 32; m++) {
        int idx = tid + m * 256;        // 0..8191
        int e = idx >> 7;
        int r = idx & 127;
        g_probsT[((size_t)(bb * NEXP + e)) * SEQ + s0 + r] = Ps[e * 130 + r];
    }
}

// ---------------------------------------------------------------------------
// Kernel 2: per-(b,e) exact top-CAP selection via 4-pass radix select on float
// bits (probs > 0 so uint ordering == float ordering). Marks mask[b, s, 0] = 1
// for selected tokens (faithful to reference's scatter-to-channel-0 semantics).
// Grid: 256 blocks (B*E), 256 threads.
// ---------------------------------------------------------------------------
__global__ void __launch_bounds__(256)
topk_mask_kernel(float* __restrict__ mask_out)
{
    __shared__ unsigned vals[SEQ];       // 32 KB
    __shared__ unsigned hist[256];
    __shared__ unsigned sel_prefix, sel_remaining;

    const int be  = blockIdx.x;
    const int tid = threadIdx.x;
    const unsigned* col = (const unsigned*)(g_probsT + (size_t)be * SEQ);

    for (int i = tid; i < SEQ; i += 256) vals[i] = col[i];
    if (tid == 0) { sel_prefix = 0u; sel_remaining = CAP; }
    __syncthreads();

    for (int pass = 0; pass < 4; pass++) {
        const int shift = 24 - 8 * pass;
        const unsigned himask = pass ? (0xFFFFFFFFu << (shift + 8)) : 0u;
        hist[tid] = 0u;
        __syncthreads();
        const unsigned pfx = sel_prefix;
        for (int i = tid; i < SEQ; i += 256) {
            unsigned u = vals[i];
            if ((u & himask) == pfx)
                atomicAdd(&hist[(u >> shift) & 255u], 1u);
        }
        __syncthreads();
        if (tid == 0) {
            unsigned rem = sel_remaining, c = 0;
            int b = 255;
            for (; b > 0; b--) { c += hist[b]; if (c >= rem) break; }
            if (c < rem) c += hist[0];  // b == 0 fallthrough
            sel_remaining = rem - (c - hist[b]);
            sel_prefix = pfx | ((unsigned)b << shift);
        }
        __syncthreads();
    }

    const unsigned thr = sel_prefix;     // exact bit pattern of CAP-th largest
    const int bb = be >> 6;              // batch
    float* mrow = mask_out + (size_t)bb * SEQ * NEXP;
    for (int i = tid; i < SEQ; i += 256) {
        if (vals[i] >= thr) mrow[(size_t)i * NEXP] = 1.0f;  // channel 0 only
    }
}

// ---------------------------------------------------------------------------
extern "C" void kernel_launch(void* const* d_in, const int* in_sizes, int n_in,
                              void* d_out, int out_size)
{
    const float* X = (const float*)d_in[0];   // [4, 8192, 4096]
    const float* W = (const float*)d_in[1];   // [64, 4096]

    float* mask   = (float*)d_out;                                  // [4,8192,64]
    float* probs  = mask  + (size_t)BATCH * SEQ * NEXP;             // [4,8192,64]
    float* logits = probs + (size_t)BATCH * SEQ * NEXP;             // [4,8192,64]

    // mask is sparse-written; clear it (async memset is graph-capturable)
    cudaMemsetAsync(mask, 0, (size_t)BATCH * SEQ * NEXP * sizeof(float));

    cudaFuncSetAttribute(router_gemm_kernel,
                         cudaFuncAttributeMaxDynamicSharedMemorySize, SMEM_BYTES);
    router_gemm_kernel<<<ROWS / TILE_R, 256, SMEM_BYTES>>>(X, W, probs, logits);

    topk_mask_kernel<<<BATCH * NEXP, 256>>>(mask);
}

// round 4
// speedup vs baseline: 2.1581x; 2.1581x over previous
#include <cuda_runtime.h>
#include <cuda_fp16.h>
#include <cstdint>

// Problem constants
#define BATCH 4
#define SEQ   8192
#define DIM   4096
#define NEXP  64
#define CAP   256
#define ROWS  (BATCH * SEQ)      // 32768

// GEMM tiling
#define TILE_R 128
#define KT     32
#define NCHUNK (DIM / KT)        // 128

// W is pre-scaled by 2^10 before fp16 split (keeps lo-parts out of subnormals);
// logits are unscaled by 2^-10 in the epilogue (exact powers of 2).
#define WSCALE   1024.0f
#define WUNSCALE 0.0009765625f

// smem: fp16 tiles, row stride 40 halves (80 bytes) -> conflict-free ldmatrix
#define AS_BYTE 80
#define AHI_OFF 0
#define ALO_OFF 10240
#define BHI_OFF 20480
#define BLO_OFF 25600
#define BUF_STRIDE 30720
#define SMEM_BYTES (2 * BUF_STRIDE)   // 61440

// scratch: transposed probs [B][E][S]
__device__ float g_probsT[(size_t)BATCH * NEXP * SEQ];

// ---------------------------------------------------------------------------
__device__ __forceinline__ uint32_t smem_u32(const void* p) {
    uint32_t a;
    asm("{ .reg .u64 t; cvta.to.shared.u64 t, %1; cvt.u32.u64 %0, t; }" : "=r"(a) : "l"(p));
    return a;
}

__device__ __forceinline__ void ldsm_x4(uint32_t& r0, uint32_t& r1, uint32_t& r2,
                                        uint32_t& r3, uint32_t addr) {
    asm volatile("ldmatrix.sync.aligned.m8n8.x4.shared.b16 {%0,%1,%2,%3}, [%4];"
                 : "=r"(r0), "=r"(r1), "=r"(r2), "=r"(r3) : "r"(addr));
}

__device__ __forceinline__ void mma_fp16(float* d, const uint32_t* a,
                                         uint32_t b0, uint32_t b1) {
    asm volatile("mma.sync.aligned.m16n8k16.row.col.f32.f16.f16.f32 "
                 "{%0,%1,%2,%3}, {%4,%5,%6,%7}, {%8,%9}, {%0,%1,%2,%3};"
                 : "+f"(d[0]), "+f"(d[1]), "+f"(d[2]), "+f"(d[3])
                 : "r"(a[0]), "r"(a[1]), "r"(a[2]), "r"(a[3]), "r"(b0), "r"(b1));
}

// ---------------------------------------------------------------------------
// Kernel 1: HMMA fp16-split router GEMM + fused softmax.
// Grid 256 x 256 threads, 2 CTAs/SM (one full wave).
// ---------------------------------------------------------------------------
__global__ void __launch_bounds__(256, 2)
router_gemm_kernel(const float* __restrict__ X, const float* __restrict__ W,
                   float* __restrict__ probs_out, float* __restrict__ logits_out)
{
    extern __shared__ char smem[];
    const uint32_t sbase = smem_u32(smem);
    const int tid  = threadIdx.x;
    const int wid  = tid >> 5;
    const int lane = tid & 31;
    const int row0 = blockIdx.x * TILE_R;

    // accumulators: 8 expert-groups (n=8 each) x 4 f32
    float d[8][4];
#pragma unroll
    for (int g = 0; g < 8; g++)
#pragma unroll
        for (int j = 0; j < 4; j++) d[g][j] = 0.f;

    // per-lane ldmatrix byte offsets (k0 = 0)
    const uint32_t a_off = (uint32_t)((wid * 16 + ((lane >> 3) & 1) * 8 + (lane & 7)) * AS_BYTE
                                      + ((lane >> 4) & 1) * 16);
    const uint32_t b_off = (uint32_t)((((lane >> 4) & 1) * 8 + (lane & 7)) * AS_BYTE
                                      + ((lane >> 3) & 1) * 16);

    // register staging for one K-chunk
    float4 xr[4];   // 128x32 fp32 / 256 thr = 4 float4
    float4 wr[2];   //  64x32 fp32 / 256 thr = 2 float4

    auto load_chunk = [&](int t) {
        const int k0 = t * KT;
#pragma unroll
        for (int m = 0; m < 4; m++) {
            int f = tid + m * 256;           // float4 slot, 8 per row
            int r = f >> 3, c4 = f & 7;
            xr[m] = *(const float4*)(X + (size_t)(row0 + r) * DIM + k0 + c4 * 4);
        }
#pragma unroll
        for (int m = 0; m < 2; m++) {
            int f = tid + m * 256;
            int e = f >> 3, c4 = f & 7;
            wr[m] = *(const float4*)(W + (size_t)e * DIM + k0 + c4 * 4);
        }
    };

    // fp16 Dekker split: hi = f16(v), lo = f16(v - hi); v - hi is exact in fp32.
    auto cvt_store = [&](float4 v, float scale, char* hi_b, char* lo_b, uint32_t byte_off) {
        v.x *= scale; v.y *= scale; v.z *= scale; v.w *= scale;
        __half2 h0 = __floats2half2_rn(v.x, v.y);
        __half2 h1 = __floats2half2_rn(v.z, v.w);
        float rx = v.x - __half2float(__low2half(h0));
        float ry = v.y - __half2float(__high2half(h0));
        float rz = v.z - __half2float(__low2half(h1));
        float rw = v.w - __half2float(__high2half(h1));
        __half2 l0 = __floats2half2_rn(rx, ry);
        __half2 l1 = __floats2half2_rn(rz, rw);
        *(uint2*)(hi_b + byte_off) = make_uint2(*(uint32_t*)&h0, *(uint32_t*)&h1);
        *(uint2*)(lo_b + byte_off) = make_uint2(*(uint32_t*)&l0, *(uint32_t*)&l1);
    };

    auto store_chunk = [&](int buf) {
        char* bp = smem + buf * BUF_STRIDE;
#pragma unroll
        for (int m = 0; m < 4; m++) {
            int f = tid + m * 256;
            int r = f >> 3, c4 = f & 7;
            cvt_store(xr[m], 1.0f, bp + AHI_OFF, bp + ALO_OFF, (uint32_t)(r * AS_BYTE + c4 * 8));
        }
#pragma unroll
        for (int m = 0; m < 2; m++) {
            int f = tid + m * 256;
            int e = f >> 3, c4 = f & 7;
            cvt_store(wr[m], WSCALE, bp + BHI_OFF, bp + BLO_OFF, (uint32_t)(e * AS_BYTE + c4 * 8));
        }
    };

    auto compute_chunk = [&](int buf) {
        const uint32_t bb = sbase + buf * BUF_STRIDE;
#pragma unroll
        for (int ks = 0; ks < 2; ks++) {
            const uint32_t kb = ks * 32;   // 16 halves = 32 bytes
            uint32_t ah[4], al[4];
            ldsm_x4(ah[0], ah[1], ah[2], ah[3], bb + AHI_OFF + a_off + kb);
            ldsm_x4(al[0], al[1], al[2], al[3], bb + ALO_OFF + a_off + kb);
#pragma unroll
            for (int gp = 0; gp < 4; gp++) {
                const uint32_t bo = b_off + gp * (16 * AS_BYTE) + kb;
                uint32_t bh[4], bl[4];
                ldsm_x4(bh[0], bh[1], bh[2], bh[3], bb + BHI_OFF + bo);
                ldsm_x4(bl[0], bl[1], bl[2], bl[3], bb + BLO_OFF + bo);
                mma_fp16(d[2 * gp],     ah, bh[0], bh[1]);
                mma_fp16(d[2 * gp],     ah, bl[0], bl[1]);
                mma_fp16(d[2 * gp],     al, bh[0], bh[1]);
                mma_fp16(d[2 * gp + 1], ah, bh[2], bh[3]);
                mma_fp16(d[2 * gp + 1], ah, bl[2], bl[3]);
                mma_fp16(d[2 * gp + 1], al, bh[2], bh[3]);
            }
        }
    };

    load_chunk(0);
    store_chunk(0);
    __syncthreads();

    for (int t = 0; t < NCHUNK; t++) {
        if (t + 1 < NCHUNK) load_chunk(t + 1);       // LDG early
        compute_chunk(t & 1);                        // long HMMA stretch hides LDG
        if (t + 1 < NCHUNK) store_chunk((t + 1) & 1);
        __syncthreads();
    }

    // ------------------------------------------------------------------
    // Epilogue: softmax per row from register accumulators (unscale by 2^-10).
    // Thread owns rows (wid*16 + lane/4) and (+8); cols 8g + 2*(lane&3)+{0,1}.
    // ------------------------------------------------------------------
    float* Ps = (float*)smem;   // [64][130] staging for probsT transpose
    const int q = lane >> 2;
    const int c2 = (lane & 3) * 2;

#pragma unroll
    for (int half = 0; half < 2; half++) {
        const int r = wid * 16 + q + half * 8;       // local row
        float v[16];
#pragma unroll
        for (int g = 0; g < 8; g++) {
            v[2 * g]     = d[g][2 * half]     * WUNSCALE;
            v[2 * g + 1] = d[g][2 * half + 1] * WUNSCALE;
        }
        float mx = v[0];
#pragma unroll
        for (int c = 1; c < 16; c++) mx = fmaxf(mx, v[c]);
        mx = fmaxf(mx, __shfl_xor_sync(0xFFFFFFFFu, mx, 1));
        mx = fmaxf(mx, __shfl_xor_sync(0xFFFFFFFFu, mx, 2));
        float p[16], ssum = 0.f;
#pragma unroll
        for (int c = 0; c < 16; c++) { p[c] = expf(v[c] - mx); ssum += p[c]; }
        ssum += __shfl_xor_sync(0xFFFFFFFFu, ssum, 1);
        ssum += __shfl_xor_sync(0xFFFFFFFFu, ssum, 2);
        const float inv = 1.0f / ssum;

        const size_t grow = (size_t)(row0 + r) * NEXP;
#pragma unroll
        for (int g = 0; g < 8; g++) {
            const int col = 8 * g + c2;
            *(float2*)(logits_out + grow + col) = make_float2(v[2 * g], v[2 * g + 1]);
            float p0 = p[2 * g] * inv, p1 = p[2 * g + 1] * inv;
            *(float2*)(probs_out + grow + col) = make_float2(p0, p1);
            Ps[col * 130 + r]       = p0;
            Ps[(col + 1) * 130 + r] = p1;
        }
    }
    __syncthreads();

    // coalesced transpose write: g_probsT[b][e][s]
    const int bb2 = row0 >> 13;
    const int s0  = row0 & (SEQ - 1);
#pragma unroll
    for (int m = 0; m < 32; m++) {
        int idx = tid + m * 256;   // 0..8191
        int e = idx >> 7, r = idx & 127;
        g_probsT[((size_t)(bb2 * NEXP + e)) * SEQ + s0 + r] = Ps[e * 130 + r];
    }
}

// ---------------------------------------------------------------------------
// Kernel 2: per-(b,e) exact top-CAP radix select (parallel suffix-scan bin
// search). Marks mask[b, s, 0] = 1 (faithful to reference channel-0 scatter).
// ---------------------------------------------------------------------------
__global__ void __launch_bounds__(256)
topk_mask_kernel(float* __restrict__ mask_out)
{
    __shared__ unsigned vals[SEQ];       // 32 KB
    __shared__ unsigned hist[256];
    __shared__ unsigned suff[256];
    __shared__ unsigned sel_prefix, sel_remaining;

    const int be  = blockIdx.x;
    const int tid = threadIdx.x;
    const unsigned* col = (const unsigned*)(g_probsT + (size_t)be * SEQ);

    for (int i = tid; i < SEQ; i += 256) vals[i] = col[i];
    if (tid == 0) { sel_prefix = 0u; sel_remaining = CAP; }
    __syncthreads();

    for (int pass = 0; pass < 4; pass++) {
        const int shift = 24 - 8 * pass;
        const unsigned himask = pass ? (0xFFFFFFFFu << (shift + 8)) : 0u;
        hist[tid] = 0u;
        __syncthreads();
        const unsigned pfx = sel_prefix;
        const unsigned rem = sel_remaining;
        for (int i = tid; i < SEQ; i += 256) {
            unsigned u = vals[i];
            if ((u & himask) == pfx)
                atomicAdd(&hist[(u >> shift) & 255u], 1u);
        }
        __syncthreads();
        // parallel suffix sum: suff[b] = sum_{i>=b} hist[i]
        suff[tid] = hist[tid];
        __syncthreads();
#pragma unroll
        for (int off = 1; off < 256; off <<= 1) {
            unsigned u = suff[tid] + ((tid + off < 256) ? suff[tid + off] : 0u);
            __syncthreads();
            suff[tid] = u;
            __syncthreads();
        }
        unsigned below = (tid < 255) ? suff[tid + 1] : 0u;
        if (suff[tid] >= rem && below < rem) {
            sel_prefix = pfx | ((unsigned)tid << shift);
            sel_remaining = rem - below;
        }
        __syncthreads();
    }

    const unsigned thr = sel_prefix;     // exact bit pattern of CAP-th largest
    const int bb = be >> 6;
    float* mrow = mask_out + (size_t)bb * SEQ * NEXP;
    for (int i = tid; i < SEQ; i += 256) {
        if (vals[i] >= thr) mrow[(size_t)i * NEXP] = 1.0f;
    }
}

// ---------------------------------------------------------------------------
extern "C" void kernel_launch(void* const* d_in, const int* in_sizes, int n_in,
                              void* d_out, int out_size)
{
    const float* X = (const float*)d_in[0];   // [4, 8192, 4096]
    const float* W = (const float*)d_in[1];   // [64, 4096]

    float* mask   = (float*)d_out;
    float* probs  = mask  + (size_t)BATCH * SEQ * NEXP;
    float* logits = probs + (size_t)BATCH * SEQ * NEXP;

    cudaMemsetAsync(mask, 0, (size_t)BATCH * SEQ * NEXP * sizeof(float));

    cudaFuncSetAttribute(router_gemm_kernel,
                         cudaFuncAttributeMaxDynamicSharedMemorySize, SMEM_BYTES);
    router_gemm_kernel<<<ROWS / TILE_R, 256, SMEM_BYTES>>>(X, W, probs, logits);

    topk_mask_kernel<<<BATCH * NEXP, 256>>>(mask);
}